// round 1
// baseline (speedup 1.0000x reference)
#include <cuda_runtime.h>
#include <math.h>

#define N_TOK 8192
#define D_IN  1024
#define D_HEAD 128

// Scratch for Q, K, V projections (device globals: no allocation in kernel_launch).
__device__ float g_Q[N_TOK * D_HEAD];
__device__ float g_K[N_TOK * D_HEAD];
__device__ float g_V[N_TOK * D_HEAD];

// ---------------------------------------------------------------------------
// Projection kernel: Out[m, c] = sum_k X[m, k] * W[c, k]   (Out = X @ W^T)
// BM=64 rows, full 128 cols, BK=32. 256 threads, 4x8 micro-tile (cols strided).
// blockIdx.y selects which of Wq/Wk/Wv (and which output buffer).
// ---------------------------------------------------------------------------
__global__ __launch_bounds__(256) void proj_kernel(
    const float* __restrict__ X, const float* __restrict__ Wq,
    const float* __restrict__ Wk, const float* __restrict__ Wv) {
  __shared__ float Xs[64][36];    // 64 x 32 (+4 pad)
  __shared__ float Ws[128][36];   // 128 x 32 (+4 pad)

  const float* W = (blockIdx.y == 0) ? Wq : (blockIdx.y == 1 ? Wk : Wv);
  float* Out     = (blockIdx.y == 0) ? g_Q : (blockIdx.y == 1 ? g_K : g_V);

  const int tid = threadIdx.x;
  const int sy = tid >> 4;        // 0..15  (row group)
  const int sx = tid & 15;        // 0..15  (col group)
  const int r0 = blockIdx.x * 64;

  float acc[4][8];
#pragma unroll
  for (int i = 0; i < 4; i++)
#pragma unroll
    for (int j = 0; j < 8; j++) acc[i][j] = 0.0f;

  for (int k0 = 0; k0 < D_IN; k0 += 32) {
    // Load X tile: 64x32 = 512 float4, 2 per thread
#pragma unroll
    for (int p = 0; p < 2; p++) {
      int idx = tid + 256 * p;
      int r = idx >> 3, c4 = idx & 7;
      float4 v = *(const float4*)&X[(size_t)(r0 + r) * D_IN + k0 + c4 * 4];
      *(float4*)&Xs[r][c4 * 4] = v;
    }
    // Load W tile: 128x32 = 1024 float4, 4 per thread
#pragma unroll
    for (int p = 0; p < 4; p++) {
      int idx = tid + 256 * p;
      int r = idx >> 3, c4 = idx & 7;
      float4 v = *(const float4*)&W[(size_t)r * D_IN + k0 + c4 * 4];
      *(float4*)&Ws[r][c4 * 4] = v;
    }
    __syncthreads();

#pragma unroll
    for (int k = 0; k < 32; k += 4) {
      float4 xv[4];
      float4 wv[8];
#pragma unroll
      for (int i = 0; i < 4; i++) xv[i] = *(float4*)&Xs[sy * 4 + i][k];
#pragma unroll
      for (int j = 0; j < 8; j++) wv[j] = *(float4*)&Ws[sx + 16 * j][k];
#pragma unroll
      for (int i = 0; i < 4; i++)
#pragma unroll
        for (int j = 0; j < 8; j++) {
          acc[i][j] += xv[i].x * wv[j].x;
          acc[i][j] += xv[i].y * wv[j].y;
          acc[i][j] += xv[i].z * wv[j].z;
          acc[i][j] += xv[i].w * wv[j].w;
        }
    }
    __syncthreads();
  }

#pragma unroll
  for (int i = 0; i < 4; i++)
#pragma unroll
    for (int j = 0; j < 8; j++)
      Out[(size_t)(r0 + sy * 4 + i) * D_HEAD + sx + 16 * j] = acc[i][j];
}

// ---------------------------------------------------------------------------
// Fused flash-attention pass (fp32, online softmax).
// BM=64 query rows per block, BN=64 key tile. 256 threads.
//   S phase : thread (sy,sx) owns S[sy*4+i][sx*4+j]   (4x4)
//   O phase : thread (sy,sx) owns O[sy*4+i][sx+16*j]  (4 rows x 8 strided cols)
// Row state m/l/alpha fully in registers (replicated across the 16 lanes of a
// row group, reduced via __shfl_xor). Only P goes through shared memory.
// Scale sqrt(128) folded into Q at load time.
// ---------------------------------------------------------------------------
#define QS_STRIDE 132
#define PS_STRIDE 68
#define FA_SMEM_FLOATS (3 * 64 * QS_STRIDE + 64 * PS_STRIDE)

__global__ __launch_bounds__(256) void flash_kernel(float* __restrict__ Out) {
  extern __shared__ float sm[];
  float* Qs = sm;                       // 64 x 132
  float* Ks = Qs + 64 * QS_STRIDE;      // 64 x 132
  float* Vs = Ks + 64 * QS_STRIDE;      // 64 x 132
  float* Ps = Vs + 64 * QS_STRIDE;      // 64 x 68

  const int tid = threadIdx.x;
  const int sy = tid >> 4;              // 0..15
  const int sx = tid & 15;              // 0..15
  const int r0 = blockIdx.x * 64;
  const float scale = 11.313708498984760f;  // sqrt(128)

  // Load Q tile (scaled): 2048 float4, 8 per thread
#pragma unroll
  for (int p = 0; p < 8; p++) {
    int idx = tid + 256 * p;
    int r = idx >> 5, c4 = idx & 31;
    float4 v = *(const float4*)&g_Q[(size_t)(r0 + r) * D_HEAD + c4 * 4];
    v.x *= scale; v.y *= scale; v.z *= scale; v.w *= scale;
    *(float4*)&Qs[r * QS_STRIDE + c4 * 4] = v;
  }

  float m_r[4], l_r[4];
  float o[4][8];
#pragma unroll
  for (int i = 0; i < 4; i++) {
    m_r[i] = -1e30f;
    l_r[i] = 0.0f;
#pragma unroll
    for (int j = 0; j < 8; j++) o[i][j] = 0.0f;
  }

  for (int t0 = 0; t0 < N_TOK; t0 += 64) {
    __syncthreads();   // previous PV done reading Vs/Ps
    // Load K & V tiles: 2048 float4 each, 8 per thread each
#pragma unroll
    for (int p = 0; p < 8; p++) {
      int idx = tid + 256 * p;
      int r = idx >> 5, c4 = idx & 31;
      *(float4*)&Ks[r * QS_STRIDE + c4 * 4] =
          *(const float4*)&g_K[(size_t)(t0 + r) * D_HEAD + c4 * 4];
      *(float4*)&Vs[r * QS_STRIDE + c4 * 4] =
          *(const float4*)&g_V[(size_t)(t0 + r) * D_HEAD + c4 * 4];
    }
    __syncthreads();

    // ---- S = Qs @ Ks^T (4x4 per thread) ----
    float s[4][4];
#pragma unroll
    for (int i = 0; i < 4; i++)
#pragma unroll
      for (int j = 0; j < 4; j++) s[i][j] = 0.0f;

#pragma unroll 4
    for (int k = 0; k < D_HEAD; k += 4) {
      float4 qv[4], kv[4];
#pragma unroll
      for (int i = 0; i < 4; i++) qv[i] = *(float4*)&Qs[(sy * 4 + i) * QS_STRIDE + k];
#pragma unroll
      for (int j = 0; j < 4; j++) kv[j] = *(float4*)&Ks[(sx * 4 + j) * QS_STRIDE + k];
#pragma unroll
      for (int i = 0; i < 4; i++)
#pragma unroll
        for (int j = 0; j < 4; j++) {
          s[i][j] += qv[i].x * kv[j].x;
          s[i][j] += qv[i].y * kv[j].y;
          s[i][j] += qv[i].z * kv[j].z;
          s[i][j] += qv[i].w * kv[j].w;
        }
    }

    // ---- online softmax (row reductions across 16 lanes) ----
    float alpha[4];
#pragma unroll
    for (int i = 0; i < 4; i++) {
      float mx = fmaxf(fmaxf(s[i][0], s[i][1]), fmaxf(s[i][2], s[i][3]));
#pragma unroll
      for (int off = 8; off >= 1; off >>= 1)
        mx = fmaxf(mx, __shfl_xor_sync(0xffffffffu, mx, off));
      float mnew = fmaxf(m_r[i], mx);
      alpha[i] = __expf(m_r[i] - mnew);
      float rs = 0.0f;
#pragma unroll
      for (int j = 0; j < 4; j++) {
        s[i][j] = __expf(s[i][j] - mnew);
        rs += s[i][j];
      }
#pragma unroll
      for (int off = 8; off >= 1; off >>= 1)
        rs += __shfl_xor_sync(0xffffffffu, rs, off);
      l_r[i] = l_r[i] * alpha[i] + rs;
      m_r[i] = mnew;
      // stash P to shared for the PV phase
#pragma unroll
      for (int j = 0; j < 4; j++)
        Ps[(sy * 4 + i) * PS_STRIDE + sx * 4 + j] = s[i][j];
    }
    __syncthreads();

    // ---- rescale O, accumulate P @ V ----
#pragma unroll
    for (int i = 0; i < 4; i++)
#pragma unroll
      for (int j = 0; j < 8; j++) o[i][j] *= alpha[i];

#pragma unroll 4
    for (int n = 0; n < 64; n++) {
      float pv[4];
#pragma unroll
      for (int i = 0; i < 4; i++) pv[i] = Ps[(sy * 4 + i) * PS_STRIDE + n];
#pragma unroll
      for (int j = 0; j < 8; j++) {
        float vv = Vs[n * QS_STRIDE + sx + 16 * j];
#pragma unroll
        for (int i = 0; i < 4; i++) o[i][j] += pv[i] * vv;
      }
    }
  }

  // ---- epilogue: divide by l, write out ----
#pragma unroll
  for (int i = 0; i < 4; i++) {
    float inv = 1.0f / l_r[i];
#pragma unroll
    for (int j = 0; j < 8; j++)
      Out[(size_t)(r0 + sy * 4 + i) * D_HEAD + sx + 16 * j] = o[i][j] * inv;
  }
}

// ---------------------------------------------------------------------------
extern "C" void kernel_launch(void* const* d_in, const int* in_sizes, int n_in,
                              void* d_out, int out_size) {
  const float* x  = (const float*)d_in[0];
  const float* Wq = (const float*)d_in[1];
  const float* Wk = (const float*)d_in[2];
  const float* Wv = (const float*)d_in[3];
  float* out = (float*)d_out;

  const int fa_smem = FA_SMEM_FLOATS * (int)sizeof(float);  // 118784 B
  cudaFuncSetAttribute(flash_kernel,
                       cudaFuncAttributeMaxDynamicSharedMemorySize, fa_smem);

  proj_kernel<<<dim3(N_TOK / 64, 3), 256>>>(x, Wq, Wk, Wv);
  flash_kernel<<<N_TOK / 64, 256, fa_smem>>>(out);
}

// round 2
// speedup vs baseline: 1.6313x; 1.6313x over previous
#include <cuda_runtime.h>
#include <math.h>

#define N_TOK 8192
#define D_IN  1024
#define D_HEAD 128

// Scratch for Q, K, V projections (device globals: no allocation in kernel_launch).
__device__ float g_Q[N_TOK * D_HEAD];
__device__ float g_K[N_TOK * D_HEAD];
__device__ float g_V[N_TOK * D_HEAD];

// ---------------------------------------------------------------------------
// f32x2 packed helpers (Blackwell FFMA2 path — only reachable via PTX)
// ---------------------------------------------------------------------------
typedef unsigned long long u64;

__device__ __forceinline__ u64 fma2(u64 a, u64 b, u64 c) {
  u64 d;
  asm("fma.rn.f32x2 %0, %1, %2, %3;" : "=l"(d) : "l"(a), "l"(b), "l"(c));
  return d;
}
__device__ __forceinline__ u64 mul2(u64 a, u64 b) {
  u64 d;
  asm("mul.rn.f32x2 %0, %1, %2;" : "=l"(d) : "l"(a), "l"(b));
  return d;
}
__device__ __forceinline__ u64 pk2(float lo, float hi) {
  u64 d;
  asm("mov.b64 %0, {%1, %2};" : "=l"(d) : "f"(lo), "f"(hi));
  return d;
}
__device__ __forceinline__ void upk2(float& lo, float& hi, u64 v) {
  asm("mov.b64 {%0, %1}, %2;" : "=f"(lo), "=f"(hi) : "l"(v));
}

// ---------------------------------------------------------------------------
// Projection kernel (unchanged from R1 — passed, ~130us): Out = X @ W^T
// ---------------------------------------------------------------------------
__global__ __launch_bounds__(256) void proj_kernel(
    const float* __restrict__ X, const float* __restrict__ Wq,
    const float* __restrict__ Wk, const float* __restrict__ Wv) {
  __shared__ float Xs[64][36];
  __shared__ float Ws[128][36];

  const float* W = (blockIdx.y == 0) ? Wq : (blockIdx.y == 1 ? Wk : Wv);
  float* Out     = (blockIdx.y == 0) ? g_Q : (blockIdx.y == 1 ? g_K : g_V);

  const int tid = threadIdx.x;
  const int sy = tid >> 4;
  const int sx = tid & 15;
  const int r0 = blockIdx.x * 64;

  float acc[4][8];
#pragma unroll
  for (int i = 0; i < 4; i++)
#pragma unroll
    for (int j = 0; j < 8; j++) acc[i][j] = 0.0f;

  for (int k0 = 0; k0 < D_IN; k0 += 32) {
#pragma unroll
    for (int p = 0; p < 2; p++) {
      int idx = tid + 256 * p;
      int r = idx >> 3, c4 = idx & 7;
      float4 v = *(const float4*)&X[(size_t)(r0 + r) * D_IN + k0 + c4 * 4];
      *(float4*)&Xs[r][c4 * 4] = v;
    }
#pragma unroll
    for (int p = 0; p < 4; p++) {
      int idx = tid + 256 * p;
      int r = idx >> 3, c4 = idx & 7;
      float4 v = *(const float4*)&W[(size_t)r * D_IN + k0 + c4 * 4];
      *(float4*)&Ws[r][c4 * 4] = v;
    }
    __syncthreads();

#pragma unroll
    for (int k = 0; k < 32; k += 4) {
      float4 xv[4];
      float4 wv[8];
#pragma unroll
      for (int i = 0; i < 4; i++) xv[i] = *(float4*)&Xs[sy * 4 + i][k];
#pragma unroll
      for (int j = 0; j < 8; j++) wv[j] = *(float4*)&Ws[sx + 16 * j][k];
#pragma unroll
      for (int i = 0; i < 4; i++)
#pragma unroll
        for (int j = 0; j < 8; j++) {
          acc[i][j] += xv[i].x * wv[j].x;
          acc[i][j] += xv[i].y * wv[j].y;
          acc[i][j] += xv[i].z * wv[j].z;
          acc[i][j] += xv[i].w * wv[j].w;
        }
    }
    __syncthreads();
  }

#pragma unroll
  for (int i = 0; i < 4; i++)
#pragma unroll
    for (int j = 0; j < 8; j++)
      Out[(size_t)(r0 + sy * 4 + i) * D_HEAD + sx + 16 * j] = acc[i][j];
}

// ---------------------------------------------------------------------------
// Flash attention v2: fp32x2 packed FMA, conflict-free smem layouts.
//
// BM=64 q-rows per CTA, BN=128 keys per tile, 256 threads (8 warps).
// Thread (sy = tid>>5, sx = tid&31):
//   owns 4 row-PAIRS  rp = sy*4+i  -> rows {8sy+2i, 8sy+2i+1}
//   owns 4 cols       c  = sx+32j  (j<4)      [S phase: key cols; PV: d cols]
// Layouts:
//   Qt[k][m]   stride 68  : q transposed, scaled; LDS.128 broadcast (sy-uniform)
//   Ks[n][k]   stride 129 : (129n+k) mod 32 = n+k -> 32-lane column reads conflict-free
//   Vs[n][d]   stride 132 : consecutive-lane reads conflict-free
//   Pt[n][m]   stride 68  : P transposed; LDS.128 broadcast in PV
// ---------------------------------------------------------------------------
#define QT_S 68
#define KS_S 129
#define VS_S 132
#define PT_S 68
#define QT_F (128 * QT_S)   // 8704 floats
#define KS_F (128 * KS_S)   // 16512
#define VS_F (128 * VS_S)   // 16896
#define PT_F (128 * PT_S)   // 8704
#define FA_SMEM_BYTES ((QT_F + KS_F + VS_F + PT_F) * 4)  // 203264

__global__ __launch_bounds__(256, 1) void flash_kernel(float* __restrict__ Out) {
  extern __shared__ float sm[];
  float* Qt = sm;
  float* Ks = Qt + QT_F;
  float* Vs = Ks + KS_F;
  float* Pt = Vs + VS_F;

  const int tid = threadIdx.x;
  const int sy = tid >> 5;            // warp id, 0..7
  const int sx = tid & 31;            // lane, 0..31
  const int r0 = blockIdx.x * 64;
  const float scale = 11.313708498984760f;  // sqrt(128)

  // ---- Qt transpose (once): Qt[k][m] = scale * Q[r0+m][k] ----
  // lane -> m (consecutive) so the 4 scalar STS hit distinct banks.
#pragma unroll
  for (int p = 0; p < 8; p++) {
    int idx = tid + 256 * p;
    int m = idx & 63, k4 = idx >> 6;               // k4: 0..31
    float4 v = *(const float4*)&g_Q[(size_t)(r0 + m) * D_HEAD + 4 * k4];
    Qt[(4 * k4 + 0) * QT_S + m] = v.x * scale;
    Qt[(4 * k4 + 1) * QT_S + m] = v.y * scale;
    Qt[(4 * k4 + 2) * QT_S + m] = v.z * scale;
    Qt[(4 * k4 + 3) * QT_S + m] = v.w * scale;
  }

  float m_[8], l_[8];
  u64 o2[4][4];
#pragma unroll
  for (int i = 0; i < 8; i++) { m_[i] = -1e30f; l_[i] = 0.0f; }
#pragma unroll
  for (int i = 0; i < 4; i++)
#pragma unroll
    for (int j = 0; j < 4; j++) o2[i][j] = 0ull;

  for (int t0 = 0; t0 < N_TOK; t0 += 128) {
    __syncthreads();   // prior tile fully consumed (Ks/Vs/Pt free)

    // ---- load K tile transpose-major safe: lane -> row n (consecutive) ----
#pragma unroll
    for (int p = 0; p < 16; p++) {
      int n  = (tid & 31) + 32 * (p >> 2);
      int k4 = (tid >> 5) + 8 * (p & 3);
      float4 v = *(const float4*)&g_K[(size_t)(t0 + n) * D_HEAD + 4 * k4];
      Ks[n * KS_S + 4 * k4 + 0] = v.x;
      Ks[n * KS_S + 4 * k4 + 1] = v.y;
      Ks[n * KS_S + 4 * k4 + 2] = v.z;
      Ks[n * KS_S + 4 * k4 + 3] = v.w;
    }
    // ---- load V tile (row-major, coalesced, conflict-free STS.128) ----
#pragma unroll
    for (int p = 0; p < 16; p++) {
      int idx = tid + 256 * p;
      int n = idx >> 5, c4 = idx & 31;
      *(float4*)&Vs[n * VS_S + 4 * c4] =
          *(const float4*)&g_V[(size_t)(t0 + n) * D_HEAD + 4 * c4];
    }
    __syncthreads();

    // ---- S = Qt^T K^T : s2[i][j] packs rows {8sy+2i, 8sy+2i+1}, col sx+32j ----
    u64 s2[4][4];
#pragma unroll
    for (int i = 0; i < 4; i++)
#pragma unroll
      for (int j = 0; j < 4; j++) s2[i][j] = 0ull;

#pragma unroll 2
    for (int k = 0; k < 128; k++) {
      const float* qrow = &Qt[k * QT_S + 8 * sy];
      ulonglong2 qA = *(const ulonglong2*)(qrow);      // pairs i=0,1
      ulonglong2 qB = *(const ulonglong2*)(qrow + 4);  // pairs i=2,3
      u64 q[4] = {qA.x, qA.y, qB.x, qB.y};
#pragma unroll
      for (int j = 0; j < 4; j++) {
        float kc = Ks[(sx + 32 * j) * KS_S + k];
        u64 kd = pk2(kc, kc);
#pragma unroll
        for (int i = 0; i < 4; i++) s2[i][j] = fma2(q[i], kd, s2[i][j]);
      }
    }

    // ---- online softmax (rows spread across the warp's 32 lanes) ----
    u64 al2[4];
#pragma unroll
    for (int i = 0; i < 4; i++) {
      float lo[4], hi[4];
#pragma unroll
      for (int j = 0; j < 4; j++) upk2(lo[j], hi[j], s2[i][j]);
      float mlo = fmaxf(fmaxf(lo[0], lo[1]), fmaxf(lo[2], lo[3]));
      float mhi = fmaxf(fmaxf(hi[0], hi[1]), fmaxf(hi[2], hi[3]));
#pragma unroll
      for (int off = 16; off >= 1; off >>= 1) {
        mlo = fmaxf(mlo, __shfl_xor_sync(0xffffffffu, mlo, off));
        mhi = fmaxf(mhi, __shfl_xor_sync(0xffffffffu, mhi, off));
      }
      float mnl = fmaxf(m_[2 * i],     mlo);
      float mnh = fmaxf(m_[2 * i + 1], mhi);
      float all = __expf(m_[2 * i]     - mnl);
      float alh = __expf(m_[2 * i + 1] - mnh);
      float rsl = 0.0f, rsh = 0.0f;
#pragma unroll
      for (int j = 0; j < 4; j++) {
        lo[j] = __expf(lo[j] - mnl); rsl += lo[j];
        hi[j] = __expf(hi[j] - mnh); rsh += hi[j];
      }
#pragma unroll
      for (int off = 16; off >= 1; off >>= 1) {
        rsl += __shfl_xor_sync(0xffffffffu, rsl, off);
        rsh += __shfl_xor_sync(0xffffffffu, rsh, off);
      }
      l_[2 * i]     = l_[2 * i]     * all + rsl;  m_[2 * i]     = mnl;
      l_[2 * i + 1] = l_[2 * i + 1] * alh + rsh;  m_[2 * i + 1] = mnh;
      al2[i] = pk2(all, alh);
      // store P transposed: Pt[col][row-pair]
#pragma unroll
      for (int j = 0; j < 4; j++)
        *(u64*)&Pt[(sx + 32 * j) * PT_S + 8 * sy + 2 * i] = pk2(lo[j], hi[j]);
    }

    // ---- rescale O accumulators (register-local) ----
#pragma unroll
    for (int i = 0; i < 4; i++)
#pragma unroll
      for (int j = 0; j < 4; j++) o2[i][j] = mul2(o2[i][j], al2[i]);

    __syncthreads();   // Pt visible to whole CTA

    // ---- O += P @ V : o2[i][j] packs rows, col d = sx+32j ----
#pragma unroll 2
    for (int n = 0; n < 128; n++) {
      const float* prow = &Pt[n * PT_S + 8 * sy];
      ulonglong2 pA = *(const ulonglong2*)(prow);
      ulonglong2 pB = *(const ulonglong2*)(prow + 4);
      u64 pp[4] = {pA.x, pA.y, pB.x, pB.y};
#pragma unroll
      for (int j = 0; j < 4; j++) {
        float vv = Vs[n * VS_S + sx + 32 * j];
        u64 vd = pk2(vv, vv);
#pragma unroll
        for (int i = 0; i < 4; i++) o2[i][j] = fma2(pp[i], vd, o2[i][j]);
      }
    }
  }

  // ---- epilogue ----
#pragma unroll
  for (int i = 0; i < 4; i++) {
    float invl = 1.0f / l_[2 * i];
    float invh = 1.0f / l_[2 * i + 1];
    int rlo = r0 + 8 * sy + 2 * i;
#pragma unroll
    for (int j = 0; j < 4; j++) {
      float lo, hi;
      upk2(lo, hi, o2[i][j]);
      Out[(size_t)rlo * D_HEAD + sx + 32 * j]       = lo * invl;
      Out[(size_t)(rlo + 1) * D_HEAD + sx + 32 * j] = hi * invh;
    }
  }
}

// ---------------------------------------------------------------------------
extern "C" void kernel_launch(void* const* d_in, const int* in_sizes, int n_in,
                              void* d_out, int out_size) {
  const float* x  = (const float*)d_in[0];
  const float* Wq = (const float*)d_in[1];
  const float* Wk = (const float*)d_in[2];
  const float* Wv = (const float*)d_in[3];
  float* out = (float*)d_out;

  cudaFuncSetAttribute(flash_kernel,
                       cudaFuncAttributeMaxDynamicSharedMemorySize,
                       FA_SMEM_BYTES);

  proj_kernel<<<dim3(N_TOK / 64, 3), 256>>>(x, Wq, Wk, Wv);
  flash_kernel<<<N_TOK / 64, 256, FA_SMEM_BYTES>>>(out);
}

// round 4
// speedup vs baseline: 3.7005x; 2.2684x over previous
#include <cuda_runtime.h>
#include <cuda_bf16.h>
#include <math.h>
#include <stdint.h>

#define N_TOK 8192
#define D_IN  1024
#define D_HEAD 128

typedef uint32_t u32;

// ---------------------------------------------------------------------------
// Scratch (device globals). Compact row-major bf16 hi/lo splits.
// Q,K: [token][128]. Vt: per 128-key tile, transposed [d][key] (128x128).
// ---------------------------------------------------------------------------
__device__ __align__(16) __nv_bfloat16 g_Qh[N_TOK * D_HEAD];
__device__ __align__(16) __nv_bfloat16 g_Ql[N_TOK * D_HEAD];
__device__ __align__(16) __nv_bfloat16 g_Kh[N_TOK * D_HEAD];
__device__ __align__(16) __nv_bfloat16 g_Kl[N_TOK * D_HEAD];
__device__ __align__(16) __nv_bfloat16 g_Vth[N_TOK * D_HEAD];
__device__ __align__(16) __nv_bfloat16 g_Vtl[N_TOK * D_HEAD];

__device__ __forceinline__ void split_bf16(float v, __nv_bfloat16& h, __nv_bfloat16& l) {
  h = __float2bfloat16(v);
  l = __float2bfloat16(v - __bfloat162float(h));
}

__device__ __forceinline__ u32 smem_u32(const void* p) {
  u32 a;
  asm("{ .reg .u64 t; cvta.to.shared.u64 t, %1; cvt.u32.u64 %0, t; }" : "=r"(a) : "l"(p));
  return a;
}
__device__ __forceinline__ void cp16(u32 dst, const void* src) {
  asm volatile("cp.async.cg.shared.global [%0], [%1], 16;" :: "r"(dst), "l"(src));
}
#define CP_COMMIT() asm volatile("cp.async.commit_group;" ::: "memory")
#define CP_WAIT0()  asm volatile("cp.async.wait_group 0;" ::: "memory")

// m16n8k16 row.col bf16 -> f32 accumulate (HMMA; portable PTX, sm_80+)
__device__ __forceinline__ void mma16816(float* d, u32 a0, u32 a1, u32 a2, u32 a3,
                                         u32 b0, u32 b1) {
  asm volatile(
      "mma.sync.aligned.m16n8k16.row.col.f32.bf16.bf16.f32 "
      "{%0,%1,%2,%3}, {%4,%5,%6,%7}, {%8,%9}, {%0,%1,%2,%3};"
      : "+f"(d[0]), "+f"(d[1]), "+f"(d[2]), "+f"(d[3])
      : "r"(a0), "r"(a1), "r"(a2), "r"(a3), "r"(b0), "r"(b1));
}

// pack {hi<<16 | lo} bf16x2 from two f32
__device__ __forceinline__ u32 cvt2(float hi, float lo) {
  u32 d;
  asm("cvt.rn.bf16x2.f32 %0, %1, %2;" : "=r"(d) : "f"(hi), "f"(lo));
  return d;
}

// ---------------------------------------------------------------------------
// Projection kernel (GEMM core from R1): fp32 X@W^T, epilogue emits bf16 hi/lo.
// y=0: Q (scaled sqrt(128)), y=1: K, y=2: V transposed per key-tile.
// ---------------------------------------------------------------------------
__global__ __launch_bounds__(256) void proj_kernel(
    const float* __restrict__ X, const float* __restrict__ Wq,
    const float* __restrict__ Wk, const float* __restrict__ Wv) {
  __shared__ float Xs[64][36];
  __shared__ float Ws[128][36];

  const int y = blockIdx.y;
  const float* W = (y == 0) ? Wq : (y == 1 ? Wk : Wv);

  const int tid = threadIdx.x;
  const int sy = tid >> 4;
  const int sx = tid & 15;
  const int r0 = blockIdx.x * 64;

  float acc[4][8];
#pragma unroll
  for (int i = 0; i < 4; i++)
#pragma unroll
    for (int j = 0; j < 8; j++) acc[i][j] = 0.0f;

  for (int k0 = 0; k0 < D_IN; k0 += 32) {
#pragma unroll
    for (int p = 0; p < 2; p++) {
      int idx = tid + 256 * p;
      int r = idx >> 3, c4 = idx & 7;
      *(float4*)&Xs[r][c4 * 4] = *(const float4*)&X[(size_t)(r0 + r) * D_IN + k0 + c4 * 4];
    }
#pragma unroll
    for (int p = 0; p < 4; p++) {
      int idx = tid + 256 * p;
      int r = idx >> 3, c4 = idx & 7;
      *(float4*)&Ws[r][c4 * 4] = *(const float4*)&W[(size_t)r * D_IN + k0 + c4 * 4];
    }
    __syncthreads();

#pragma unroll
    for (int k = 0; k < 32; k += 4) {
      float4 xv[4];
      float4 wv[8];
#pragma unroll
      for (int i = 0; i < 4; i++) xv[i] = *(float4*)&Xs[sy * 4 + i][k];
#pragma unroll
      for (int j = 0; j < 8; j++) wv[j] = *(float4*)&Ws[sx + 16 * j][k];
#pragma unroll
      for (int i = 0; i < 4; i++)
#pragma unroll
        for (int j = 0; j < 8; j++) {
          acc[i][j] += xv[i].x * wv[j].x;
          acc[i][j] += xv[i].y * wv[j].y;
          acc[i][j] += xv[i].z * wv[j].z;
          acc[i][j] += xv[i].w * wv[j].w;
        }
    }
    __syncthreads();
  }

  const float scale = 11.313708498984760f;  // sqrt(128)
#pragma unroll
  for (int i = 0; i < 4; i++)
#pragma unroll
    for (int j = 0; j < 8; j++) {
      int R = r0 + sy * 4 + i;   // token
      int c = sx + 16 * j;       // head dim
      __nv_bfloat16 h, l;
      if (y == 0) {
        split_bf16(acc[i][j] * scale, h, l);
        g_Qh[(size_t)R * D_HEAD + c] = h;
        g_Ql[(size_t)R * D_HEAD + c] = l;
      } else if (y == 1) {
        split_bf16(acc[i][j], h, l);
        g_Kh[(size_t)R * D_HEAD + c] = h;
        g_Kl[(size_t)R * D_HEAD + c] = l;
      } else {
        split_bf16(acc[i][j], h, l);
        size_t idx = (size_t)(R >> 7) * 16384 + (size_t)c * 128 + (R & 127);
        g_Vth[idx] = h;
        g_Vtl[idx] = l;
      }
    }
}

// ---------------------------------------------------------------------------
// HMMA flash kernel. BM=64, BN=128, 256 threads (8 warps).
// warp w: row-group rg=w&3 (rows 16rg..16rg+15), key-half kh=w>>2 (keys 64kh..+63).
// Smem rows padded to 272B (16 mod 128) -> frag loads map to banks 4g+t (conflict-free).
// ---------------------------------------------------------------------------
#define RSTR 272                      // bytes per smem row (128 bf16 payload + pad)
#define SQH 0
#define SQL (SQH + 64 * RSTR)         // 17408
#define SKH (SQL + 64 * RSTR)         // 34816
#define SKL (SKH + 128 * RSTR)        // 69632
#define SVH (SKL + 128 * RSTR)        // 104448
#define SVL (SVH + 128 * RSTR)        // 139264
#define SRED (SVL + 128 * RSTR)       // 174080
#define ATT_SMEM (SRED + 1024)        // 175104

__global__ __launch_bounds__(256, 1) void attn_kernel(float* __restrict__ Out) {
  extern __shared__ __align__(16) char smem[];
  const u32 sb = smem_u32(smem);

  const int tid = threadIdx.x;
  const int w   = tid >> 5;
  const int lane = tid & 31;
  const int g = lane >> 2;      // 0..7
  const int t = lane & 3;       // 0..3
  const int rg = w & 3;
  const int kh = w >> 2;
  const int qb = blockIdx.x;
  const int r0 = 16 * rg + g;
  const int r1 = r0 + 8;

  // ---- load Q hi/lo tiles (once) ----
  {
    const char* gqh = (const char*)g_Qh + (size_t)qb * 64 * 256;
    const char* gql = (const char*)g_Ql + (size_t)qb * 64 * 256;
#pragma unroll
    for (int p = 0; p < 4; p++) {
      int idx = tid + 256 * p;         // 0..1023
      int row = idx >> 4, sub = idx & 15;
      cp16(sb + SQH + row * RSTR + sub * 16, gqh + idx * 16);
      cp16(sb + SQL + row * RSTR + sub * 16, gql + idx * 16);
    }
    CP_COMMIT();
    CP_WAIT0();
  }

  // frag base byte-offsets into smem
  const int oQh = SQH + r0 * RSTR + t * 4;
  const int oKh = SKH + (64 * kh + g) * RSTR + t * 4;
  const int oVh = SVH + g * RSTR + t * 4 + 128 * kh;   // +64kh keys * 2B

  float o[16][4];
#pragma unroll
  for (int i = 0; i < 16; i++)
#pragma unroll
    for (int j = 0; j < 4; j++) o[i][j] = 0.0f;
  float m0 = -1e30f, m1 = -1e30f, l0 = 0.0f, l1 = 0.0f;

  float* redm = (float*)(smem + SRED);
  float* redl = redm + 128;

  for (int tile = 0; tile < 64; ++tile) {
    __syncthreads();   // prior tile's smem fully consumed
    {
      const char* gkh = (const char*)g_Kh  + (size_t)tile * 32768;
      const char* gkl = (const char*)g_Kl  + (size_t)tile * 32768;
      const char* gvh = (const char*)g_Vth + (size_t)tile * 32768;
      const char* gvl = (const char*)g_Vtl + (size_t)tile * 32768;
#pragma unroll
      for (int p = 0; p < 8; p++) {
        int idx = tid + 256 * p;       // 0..2047
        int row = idx >> 4, sub = idx & 15;
        int so = row * RSTR + sub * 16;
        cp16(sb + SKH + so, gkh + idx * 16);
        cp16(sb + SKL + so, gkl + idx * 16);
        cp16(sb + SVH + so, gvh + idx * 16);
        cp16(sb + SVL + so, gvl + idx * 16);
      }
      CP_COMMIT();
      CP_WAIT0();
    }
    __syncthreads();

    // ---- S = Q K^T over this warp's 64 keys (hi*hi + lo*hi + hi*lo) ----
    float s[8][4];
#pragma unroll
    for (int i = 0; i < 8; i++)
#pragma unroll
      for (int j = 0; j < 4; j++) s[i][j] = 0.0f;

    for (int kc = 0; kc < 8; kc++) {
      const int qo = oQh + kc * 32;
      u32 ah0 = *(const u32*)(smem + qo);
      u32 ah1 = *(const u32*)(smem + qo + 8 * RSTR);
      u32 ah2 = *(const u32*)(smem + qo + 16);
      u32 ah3 = *(const u32*)(smem + qo + 8 * RSTR + 16);
      u32 al0 = *(const u32*)(smem + qo + 17408);
      u32 al1 = *(const u32*)(smem + qo + 17408 + 8 * RSTR);
      u32 al2 = *(const u32*)(smem + qo + 17408 + 16);
      u32 al3 = *(const u32*)(smem + qo + 17408 + 8 * RSTR + 16);
#pragma unroll
      for (int nf = 0; nf < 8; nf++) {
        const int bo = oKh + nf * 8 * RSTR + kc * 32;
        u32 bh0 = *(const u32*)(smem + bo);
        u32 bh1 = *(const u32*)(smem + bo + 16);
        mma16816(s[nf], ah0, ah1, ah2, ah3, bh0, bh1);
        mma16816(s[nf], al0, al1, al2, al3, bh0, bh1);
        u32 bl0 = *(const u32*)(smem + bo + 34816);
        u32 bl1 = *(const u32*)(smem + bo + 34816 + 16);
        mma16816(s[nf], ah0, ah1, ah2, ah3, bl0, bl1);
      }
    }

    // ---- online softmax ----
    float mt0 = -1e30f, mt1 = -1e30f;
#pragma unroll
    for (int nf = 0; nf < 8; nf++) {
      mt0 = fmaxf(mt0, fmaxf(s[nf][0], s[nf][1]));
      mt1 = fmaxf(mt1, fmaxf(s[nf][2], s[nf][3]));
    }
#pragma unroll
    for (int off = 1; off <= 2; off <<= 1) {
      mt0 = fmaxf(mt0, __shfl_xor_sync(0xffffffffu, mt0, off));
      mt1 = fmaxf(mt1, __shfl_xor_sync(0xffffffffu, mt1, off));
    }
    if (t == 0) { redm[kh * 64 + r0] = mt0; redm[kh * 64 + r1] = mt1; }
    __syncthreads();
    mt0 = fmaxf(mt0, redm[(1 ^ kh) * 64 + r0]);
    mt1 = fmaxf(mt1, redm[(1 ^ kh) * 64 + r1]);
    const float mn0 = fmaxf(m0, mt0), mn1 = fmaxf(m1, mt1);
    const float a0f = __expf(m0 - mn0), a1f = __expf(m1 - mn1);
    m0 = mn0; m1 = mn1;

    float sum0 = 0.0f, sum1 = 0.0f;
#pragma unroll
    for (int nf = 0; nf < 8; nf++) {
      s[nf][0] = __expf(s[nf][0] - mn0); sum0 += s[nf][0];
      s[nf][1] = __expf(s[nf][1] - mn0); sum0 += s[nf][1];
      s[nf][2] = __expf(s[nf][2] - mn1); sum1 += s[nf][2];
      s[nf][3] = __expf(s[nf][3] - mn1); sum1 += s[nf][3];
    }
#pragma unroll
    for (int off = 1; off <= 2; off <<= 1) {
      sum0 += __shfl_xor_sync(0xffffffffu, sum0, off);
      sum1 += __shfl_xor_sync(0xffffffffu, sum1, off);
    }
    if (t == 0) { redl[kh * 64 + r0] = sum0; redl[kh * 64 + r1] = sum1; }

    // rescale O while the other half catches up
#pragma unroll
    for (int i = 0; i < 16; i++) {
      o[i][0] *= a0f; o[i][1] *= a0f;
      o[i][2] *= a1f; o[i][3] *= a1f;
    }
    __syncthreads();
    l0 = l0 * a0f + sum0 + redl[(1 ^ kh) * 64 + r0];
    l1 = l1 * a1f + sum1 + redl[(1 ^ kh) * 64 + r1];

    // ---- pack P hi/lo into PV A-frags (registers only) ----
    u32 ph[4][4], pl[4][4];
#pragma unroll
    for (int c = 0; c < 4; c++) {
      float e[8] = { s[2*c][0],   s[2*c][1],   s[2*c][2],   s[2*c][3],
                     s[2*c+1][0], s[2*c+1][1], s[2*c+1][2], s[2*c+1][3] };
      // a0:(g, k2t|2t+1)  a1:(g+8, ..)  a2:(g, k+8..)  a3:(g+8, k+8..)
      const int map[4][2] = {{0,1},{2,3},{4,5},{6,7}};
#pragma unroll
      for (int q = 0; q < 4; q++) {
        float x0 = e[map[q][0]], x1 = e[map[q][1]];
        u32 hp = cvt2(x1, x0);
        float h0 = __uint_as_float(hp << 16);
        float h1 = __uint_as_float(hp & 0xffff0000u);
        ph[c][q] = hp;
        pl[c][q] = cvt2(x1 - h1, x0 - h0);
      }
    }

    // ---- O += P V over this warp's 64 keys ----
    for (int c = 0; c < 4; c++) {
#pragma unroll
      for (int nf2 = 0; nf2 < 16; nf2++) {
        const int vb = oVh + nf2 * 8 * RSTR + c * 32;
        u32 bh0 = *(const u32*)(smem + vb);
        u32 bh1 = *(const u32*)(smem + vb + 16);
        mma16816(o[nf2], ph[c][0], ph[c][1], ph[c][2], ph[c][3], bh0, bh1);
        mma16816(o[nf2], pl[c][0], pl[c][1], pl[c][2], pl[c][3], bh0, bh1);
        u32 bl0 = *(const u32*)(smem + vb + 34816);
        u32 bl1 = *(const u32*)(smem + vb + 34816 + 16);
        mma16816(o[nf2], ph[c][0], ph[c][1], ph[c][2], ph[c][3], bl0, bl1);
      }
    }
  }

  // ---- epilogue: combine the two key-half partial O's, normalize, store ----
  float* Ob = (float*)(smem + SKH);   // 64 x 128 f32 (reuses K tile space)
  if (kh == 0) {
#pragma unroll
    for (int nf2 = 0; nf2 < 16; nf2++) {
      int c0 = 8 * nf2 + 2 * t;
      Ob[r0 * 128 + c0]     = o[nf2][0];
      Ob[r0 * 128 + c0 + 1] = o[nf2][1];
      Ob[r1 * 128 + c0]     = o[nf2][2];
      Ob[r1 * 128 + c0 + 1] = o[nf2][3];
    }
  }
  __syncthreads();
  if (kh == 1) {
    const float inv0 = 1.0f / l0, inv1 = 1.0f / l1;
#pragma unroll
    for (int nf2 = 0; nf2 < 16; nf2++) {
      int c0 = 8 * nf2 + 2 * t;
      float v00 = (o[nf2][0] + Ob[r0 * 128 + c0])     * inv0;
      float v01 = (o[nf2][1] + Ob[r0 * 128 + c0 + 1]) * inv0;
      float v10 = (o[nf2][2] + Ob[r1 * 128 + c0])     * inv1;
      float v11 = (o[nf2][3] + Ob[r1 * 128 + c0 + 1]) * inv1;
      *(float2*)&Out[(size_t)(qb * 64 + r0) * D_HEAD + c0] = make_float2(v00, v01);
      *(float2*)&Out[(size_t)(qb * 64 + r1) * D_HEAD + c0] = make_float2(v10, v11);
    }
  }
}

// ---------------------------------------------------------------------------
extern "C" void kernel_launch(void* const* d_in, const int* in_sizes, int n_in,
                              void* d_out, int out_size) {
  const float* x  = (const float*)d_in[0];
  const float* Wq = (const float*)d_in[1];
  const float* Wk = (const float*)d_in[2];
  const float* Wv = (const float*)d_in[3];
  float* out = (float*)d_out;

  cudaFuncSetAttribute(attn_kernel,
                       cudaFuncAttributeMaxDynamicSharedMemorySize, ATT_SMEM);

  proj_kernel<<<dim3(N_TOK / 64, 3), 256>>>(x, Wq, Wk, Wv);
  attn_kernel<<<N_TOK / 64, 256, ATT_SMEM>>>(out);
}

// round 5
// speedup vs baseline: 4.3060x; 1.1636x over previous
#include <cuda_runtime.h>
#include <cuda_bf16.h>
#include <math.h>
#include <stdint.h>

#define N_TOK 8192
#define D_IN  1024
#define D_HEAD 128

typedef uint32_t u32;

// ---------------------------------------------------------------------------
// Device-global scratch.
// ---------------------------------------------------------------------------
__device__ __align__(16) __nv_bfloat16 g_Xh[(size_t)N_TOK * D_IN];
__device__ __align__(16) __nv_bfloat16 g_Xl[(size_t)N_TOK * D_IN];
__device__ __align__(16) __nv_bfloat16 g_Wh[3 * D_HEAD * D_IN];
__device__ __align__(16) __nv_bfloat16 g_Wl[3 * D_HEAD * D_IN];
__device__ __align__(16) __nv_bfloat16 g_Qh[N_TOK * D_HEAD];
__device__ __align__(16) __nv_bfloat16 g_Ql[N_TOK * D_HEAD];
__device__ __align__(16) __nv_bfloat16 g_Kh[N_TOK * D_HEAD];
__device__ __align__(16) __nv_bfloat16 g_Kl[N_TOK * D_HEAD];
__device__ __align__(16) __nv_bfloat16 g_Vth[N_TOK * D_HEAD];
__device__ __align__(16) __nv_bfloat16 g_Vtl[N_TOK * D_HEAD];

__device__ __forceinline__ void split_bf16(float v, __nv_bfloat16& h, __nv_bfloat16& l) {
  h = __float2bfloat16(v);
  l = __float2bfloat16(v - __bfloat162float(h));
}

__device__ __forceinline__ u32 smem_u32(const void* p) {
  u32 a;
  asm("{ .reg .u64 t; cvta.to.shared.u64 t, %1; cvt.u32.u64 %0, t; }" : "=r"(a) : "l"(p));
  return a;
}
__device__ __forceinline__ void cp16(u32 dst, const void* src) {
  asm volatile("cp.async.cg.shared.global [%0], [%1], 16;" :: "r"(dst), "l"(src));
}
#define CP_COMMIT() asm volatile("cp.async.commit_group;" ::: "memory")
#define CP_WAIT0()  asm volatile("cp.async.wait_group 0;" ::: "memory")
#define CP_WAIT1()  asm volatile("cp.async.wait_group 1;" ::: "memory")

// m16n8k16 row.col bf16 -> f32 (HMMA; portable PTX)
__device__ __forceinline__ void mma16816(float* d, u32 a0, u32 a1, u32 a2, u32 a3,
                                         u32 b0, u32 b1) {
  asm volatile(
      "mma.sync.aligned.m16n8k16.row.col.f32.bf16.bf16.f32 "
      "{%0,%1,%2,%3}, {%4,%5,%6,%7}, {%8,%9}, {%0,%1,%2,%3};"
      : "+f"(d[0]), "+f"(d[1]), "+f"(d[2]), "+f"(d[3])
      : "r"(a0), "r"(a1), "r"(a2), "r"(a3), "r"(b0), "r"(b1));
}
__device__ __forceinline__ u32 cvt2(float hi, float lo) {
  u32 d;
  asm("cvt.rn.bf16x2.f32 %0, %1, %2;" : "=r"(d) : "f"(hi), "f"(lo));
  return d;
}

// ---------------------------------------------------------------------------
// Split kernels: fp32 -> bf16 hi/lo. 8 elems/thread, vector IO.
// ---------------------------------------------------------------------------
__device__ __forceinline__ void split8_store(const float* v, __nv_bfloat16* dh,
                                             __nv_bfloat16* dl) {
  u32 hw[4], lw[4];
#pragma unroll
  for (int j = 0; j < 4; j++) {
    __nv_bfloat16 h0, l0, h1, l1;
    split_bf16(v[2 * j], h0, l0);
    split_bf16(v[2 * j + 1], h1, l1);
    hw[j] = ((u32)__bfloat16_as_ushort(h1) << 16) | __bfloat16_as_ushort(h0);
    lw[j] = ((u32)__bfloat16_as_ushort(l1) << 16) | __bfloat16_as_ushort(l0);
  }
  *(uint4*)dh = make_uint4(hw[0], hw[1], hw[2], hw[3]);
  *(uint4*)dl = make_uint4(lw[0], lw[1], lw[2], lw[3]);
}

__global__ __launch_bounds__(256) void split_x_kernel(const float* __restrict__ X) {
  size_t i = ((size_t)blockIdx.x * 256 + threadIdx.x) * 8;
  float4 f0 = *(const float4*)&X[i];
  float4 f1 = *(const float4*)&X[i + 4];
  float v[8] = {f0.x, f0.y, f0.z, f0.w, f1.x, f1.y, f1.z, f1.w};
  split8_store(v, &g_Xh[i], &g_Xl[i]);
}

__global__ __launch_bounds__(256) void split_w_kernel(
    const float* __restrict__ Wq, const float* __restrict__ Wk,
    const float* __restrict__ Wv) {
  const int y = blockIdx.y;
  const float* W = (y == 0) ? Wq : (y == 1 ? Wk : Wv);
  size_t i = ((size_t)blockIdx.x * 256 + threadIdx.x) * 8;
  float4 f0 = *(const float4*)&W[i];
  float4 f1 = *(const float4*)&W[i + 4];
  float v[8] = {f0.x, f0.y, f0.z, f0.w, f1.x, f1.y, f1.z, f1.w};
  size_t o = (size_t)y * D_HEAD * D_IN + i;
  split8_store(v, &g_Wh[o], &g_Wl[o]);
}

// ---------------------------------------------------------------------------
// HMMA projection: Out[8192,128] = X @ W^T (hi/lo 3-MMA splits), K=1024.
// BM=128, 256 threads, 8 warps (warp w: rows 16w..16w+15, all 128 cols).
// Static smem 40KB, 2 CTAs/SM. Epilogue emits bf16 hi/lo into attention layouts.
// ---------------------------------------------------------------------------
#define PSTR 80     // bytes per smem row (32 bf16 payload + pad); banks (20g+t)%32 distinct
#define PXH 0
#define PXL 10240
#define PWH 20480
#define PWL 30720

__global__ __launch_bounds__(256, 2) void proj_mma_kernel() {
  __shared__ __align__(16) char psm[40960];
  const u32 pb = smem_u32(psm);

  const int y = blockIdx.y;
  const int bm = blockIdx.x;
  const int tid = threadIdx.x;
  const int w = tid >> 5;
  const int lane = tid & 31;
  const int g = lane >> 2;
  const int t = lane & 3;

  const char* xh = (const char*)g_Xh;
  const char* xl = (const char*)g_Xl;
  const char* wh = (const char*)(g_Wh + (size_t)y * D_HEAD * D_IN);
  const char* wl = (const char*)(g_Wl + (size_t)y * D_HEAD * D_IN);

  float o[16][4];
#pragma unroll
  for (int i = 0; i < 16; i++)
#pragma unroll
    for (int j = 0; j < 4; j++) o[i][j] = 0.0f;

#pragma unroll 1
  for (int k0 = 0; k0 < D_IN; k0 += 32) {
#pragma unroll
    for (int p = 0; p < 2; p++) {
      int idx = tid + 256 * p;           // 0..511
      int row = idx >> 2, sub = idx & 3;
      int so = row * PSTR + sub * 16;
      size_t xoff = ((size_t)(bm * 128 + row) * D_IN + k0) * 2 + sub * 16;
      size_t woff = ((size_t)row * D_IN + k0) * 2 + sub * 16;
      cp16(pb + PXH + so, xh + xoff);
      cp16(pb + PXL + so, xl + xoff);
      cp16(pb + PWH + so, wh + woff);
      cp16(pb + PWL + so, wl + woff);
    }
    CP_COMMIT();
    CP_WAIT0();
    __syncthreads();

    const int oX = (16 * w + g) * PSTR + t * 4;
#pragma unroll
    for (int kc = 0; kc < 2; kc++) {
      const int qo = oX + kc * 32;
      u32 ah0 = *(const u32*)(psm + PXH + qo);
      u32 ah1 = *(const u32*)(psm + PXH + qo + 8 * PSTR);
      u32 ah2 = *(const u32*)(psm + PXH + qo + 16);
      u32 ah3 = *(const u32*)(psm + PXH + qo + 8 * PSTR + 16);
      u32 al0 = *(const u32*)(psm + PXL + qo);
      u32 al1 = *(const u32*)(psm + PXL + qo + 8 * PSTR);
      u32 al2 = *(const u32*)(psm + PXL + qo + 16);
      u32 al3 = *(const u32*)(psm + PXL + qo + 8 * PSTR + 16);
#pragma unroll
      for (int nf = 0; nf < 16; nf++) {
        const int bo = (8 * nf + g) * PSTR + t * 4 + kc * 32;
        u32 bh0 = *(const u32*)(psm + PWH + bo);
        u32 bh1 = *(const u32*)(psm + PWH + bo + 16);
        mma16816(o[nf], ah0, ah1, ah2, ah3, bh0, bh1);
        mma16816(o[nf], al0, al1, al2, al3, bh0, bh1);
        u32 bl0 = *(const u32*)(psm + PWL + bo);
        u32 bl1 = *(const u32*)(psm + PWL + bo + 16);
        mma16816(o[nf], ah0, ah1, ah2, ah3, bl0, bl1);
      }
    }
    __syncthreads();
  }

  const float scale = 11.313708498984760f;  // sqrt(128)
#pragma unroll
  for (int nf = 0; nf < 16; nf++) {
    int c0 = 8 * nf + 2 * t;
    int R0 = bm * 128 + 16 * w + g;
#pragma unroll
    for (int q = 0; q < 4; q++) {
      int R = R0 + (q >> 1) * 8;
      int c = c0 + (q & 1);
      float v = o[nf][q];
      __nv_bfloat16 h, l;
      if (y == 0) {
        split_bf16(v * scale, h, l);
        g_Qh[(size_t)R * D_HEAD + c] = h;
        g_Ql[(size_t)R * D_HEAD + c] = l;
      } else if (y == 1) {
        split_bf16(v, h, l);
        g_Kh[(size_t)R * D_HEAD + c] = h;
        g_Kl[(size_t)R * D_HEAD + c] = l;
      } else {
        split_bf16(v, h, l);
        size_t idx = (size_t)(R >> 7) * 16384 + (size_t)c * 128 + (R & 127);
        g_Vth[idx] = h;
        g_Vtl[idx] = l;
      }
    }
  }
}

// ---------------------------------------------------------------------------
// Pipelined HMMA flash kernel. BM=64, BN=64/tile, 128 tiles, double-buffered.
// 256 threads (8 warps): rg=w&3 -> rows 16rg..+15, kh=w>>2 -> 32-key half.
// K rows stride 272B, V rows stride 144B: frag LDS banks (4g+t) conflict-free.
// ---------------------------------------------------------------------------
#define RSTR 272
#define VSTR 144
#define SQH 0
#define SQL 17408
#define SBUF 34816
#define BKH 0
#define BKL 17408
#define BVH 34816
#define BVL 53248
#define BUFSZ 71680
#define SRED (SBUF + 2 * BUFSZ)        // 178176
#define ATT_SMEM (SRED + 1024)         // 179200

__global__ __launch_bounds__(256, 1) void attn_kernel(float* __restrict__ Out) {
  extern __shared__ __align__(16) char smem[];
  const u32 sb = smem_u32(smem);

  const int tid = threadIdx.x;
  const int w = tid >> 5;
  const int lane = tid & 31;
  const int g = lane >> 2;
  const int t = lane & 3;
  const int rg = w & 3;
  const int kh = w >> 2;
  const int qb = blockIdx.x;
  const int r0 = 16 * rg + g;
  const int r1 = r0 + 8;

  // tile loader: K (64 keys x 128 dims hi/lo) + Vt (128 d x 64 keys hi/lo)
  auto issue_tile = [&](int tile, int b) {
    const u32 base = sb + SBUF + b * BUFSZ;
    const char* gkh = (const char*)g_Kh + (size_t)tile * 16384;
    const char* gkl = (const char*)g_Kl + (size_t)tile * 16384;
    const size_t vbase = (size_t)(tile >> 1) * 32768 + (size_t)(tile & 1) * 128;
    const char* gvh = (const char*)g_Vth + vbase;
    const char* gvl = (const char*)g_Vtl + vbase;
#pragma unroll
    for (int p = 0; p < 4; p++) {
      int idx = tid + 256 * p;           // 0..1023
      int kr = idx >> 4, ks = idx & 15;
      int kso = kr * RSTR + ks * 16;
      cp16(base + BKH + kso, gkh + idx * 16);
      cp16(base + BKL + kso, gkl + idx * 16);
      int vd = idx >> 3, vs = idx & 7;
      int vso = vd * VSTR + vs * 16;
      size_t voff = (size_t)vd * 256 + vs * 16;
      cp16(base + BVH + vso, gvh + voff);
      cp16(base + BVL + vso, gvl + voff);
    }
  };

  // prologue: Q + tile0 in group 0, tile1 in group 1
  {
    const char* gqh = (const char*)g_Qh + (size_t)qb * 16384;
    const char* gql = (const char*)g_Ql + (size_t)qb * 16384;
#pragma unroll
    for (int p = 0; p < 4; p++) {
      int idx = tid + 256 * p;           // 0..1023
      int row = idx >> 4, sub = idx & 15;
      int so = row * RSTR + sub * 16;
      cp16(sb + SQH + so, gqh + idx * 16);
      cp16(sb + SQL + so, gql + idx * 16);
    }
    issue_tile(0, 0);
    CP_COMMIT();
    issue_tile(1, 1);
    CP_COMMIT();
  }

  const int oQ = SQH + r0 * RSTR + t * 4;

  float o[16][4];
#pragma unroll
  for (int i = 0; i < 16; i++)
#pragma unroll
    for (int j = 0; j < 4; j++) o[i][j] = 0.0f;
  float m0 = -1e30f, m1 = -1e30f, l0 = 0.0f, l1 = 0.0f;

  float* redm = (float*)(smem + SRED);
  float* redl = redm + 128;

#pragma unroll 1
  for (int tile = 0; tile < 128; ++tile) {
    if (tile < 127) CP_WAIT1(); else CP_WAIT0();
    __syncthreads();

    const int bb = SBUF + (tile & 1) * BUFSZ;
    const int oK = bb + BKH + (32 * kh + g) * RSTR + t * 4;
    const int oV = bb + BVH + g * VSTR + t * 4 + kh * 64;

    // ---- S = Q K^T over this warp's 32 keys ----
    float s[4][4];
#pragma unroll
    for (int i = 0; i < 4; i++)
#pragma unroll
      for (int j = 0; j < 4; j++) s[i][j] = 0.0f;

#pragma unroll
    for (int kc = 0; kc < 8; kc++) {
      const int qo = oQ + kc * 32;
      u32 ah0 = *(const u32*)(smem + qo);
      u32 ah1 = *(const u32*)(smem + qo + 8 * RSTR);
      u32 ah2 = *(const u32*)(smem + qo + 16);
      u32 ah3 = *(const u32*)(smem + qo + 8 * RSTR + 16);
      u32 al0 = *(const u32*)(smem + qo + 17408);
      u32 al1 = *(const u32*)(smem + qo + 17408 + 8 * RSTR);
      u32 al2 = *(const u32*)(smem + qo + 17408 + 16);
      u32 al3 = *(const u32*)(smem + qo + 17408 + 8 * RSTR + 16);
#pragma unroll
      for (int nf = 0; nf < 4; nf++) {
        const int bo = oK + nf * 8 * RSTR + kc * 32;
        u32 bh0 = *(const u32*)(smem + bo);
        u32 bh1 = *(const u32*)(smem + bo + 16);
        mma16816(s[nf], ah0, ah1, ah2, ah3, bh0, bh1);
        mma16816(s[nf], al0, al1, al2, al3, bh0, bh1);
        u32 bl0 = *(const u32*)(smem + bo + 17408);
        u32 bl1 = *(const u32*)(smem + bo + 17408 + 16);
        mma16816(s[nf], ah0, ah1, ah2, ah3, bl0, bl1);
      }
    }

    // ---- online softmax (cross-kh combine via smem) ----
    float mt0 = -1e30f, mt1 = -1e30f;
#pragma unroll
    for (int nf = 0; nf < 4; nf++) {
      mt0 = fmaxf(mt0, fmaxf(s[nf][0], s[nf][1]));
      mt1 = fmaxf(mt1, fmaxf(s[nf][2], s[nf][3]));
    }
#pragma unroll
    for (int off = 1; off <= 2; off <<= 1) {
      mt0 = fmaxf(mt0, __shfl_xor_sync(0xffffffffu, mt0, off));
      mt1 = fmaxf(mt1, __shfl_xor_sync(0xffffffffu, mt1, off));
    }
    if (t == 0) { redm[kh * 64 + r0] = mt0; redm[kh * 64 + r1] = mt1; }
    __syncthreads();
    mt0 = fmaxf(mt0, redm[(1 ^ kh) * 64 + r0]);
    mt1 = fmaxf(mt1, redm[(1 ^ kh) * 64 + r1]);
    const float mn0 = fmaxf(m0, mt0), mn1 = fmaxf(m1, mt1);
    const float a0f = __expf(m0 - mn0), a1f = __expf(m1 - mn1);
    m0 = mn0; m1 = mn1;

    float sum0 = 0.0f, sum1 = 0.0f;
#pragma unroll
    for (int nf = 0; nf < 4; nf++) {
      s[nf][0] = __expf(s[nf][0] - mn0); sum0 += s[nf][0];
      s[nf][1] = __expf(s[nf][1] - mn0); sum0 += s[nf][1];
      s[nf][2] = __expf(s[nf][2] - mn1); sum1 += s[nf][2];
      s[nf][3] = __expf(s[nf][3] - mn1); sum1 += s[nf][3];
    }
#pragma unroll
    for (int off = 1; off <= 2; off <<= 1) {
      sum0 += __shfl_xor_sync(0xffffffffu, sum0, off);
      sum1 += __shfl_xor_sync(0xffffffffu, sum1, off);
    }
    if (t == 0) { redl[kh * 64 + r0] = sum0; redl[kh * 64 + r1] = sum1; }

#pragma unroll
    for (int i = 0; i < 16; i++) {
      o[i][0] *= a0f; o[i][1] *= a0f;
      o[i][2] *= a1f; o[i][3] *= a1f;
    }
    __syncthreads();
    l0 = l0 * a0f + sum0 + redl[(1 ^ kh) * 64 + r0];
    l1 = l1 * a1f + sum1 + redl[(1 ^ kh) * 64 + r1];

    // ---- pack P hi/lo into PV A-frags (registers only) ----
    u32 ph[2][4], pl[2][4];
#pragma unroll
    for (int c = 0; c < 2; c++) {
      float e[8] = { s[2*c][0],   s[2*c][1],   s[2*c][2],   s[2*c][3],
                     s[2*c+1][0], s[2*c+1][1], s[2*c+1][2], s[2*c+1][3] };
      const int map[4][2] = {{0,1},{2,3},{4,5},{6,7}};
#pragma unroll
      for (int q = 0; q < 4; q++) {
        float x0 = e[map[q][0]], x1 = e[map[q][1]];
        u32 hp = cvt2(x1, x0);
        float h0 = __uint_as_float(hp << 16);
        float h1 = __uint_as_float(hp & 0xffff0000u);
        ph[c][q] = hp;
        pl[c][q] = cvt2(x1 - h1, x0 - h0);
      }
    }

    // ---- O += P V over this warp's 32 keys ----
#pragma unroll
    for (int c = 0; c < 2; c++) {
#pragma unroll
      for (int nf2 = 0; nf2 < 16; nf2++) {
        const int vb = oV + nf2 * 8 * VSTR + c * 32;
        u32 bh0 = *(const u32*)(smem + vb);
        u32 bh1 = *(const u32*)(smem + vb + 16);
        mma16816(o[nf2], ph[c][0], ph[c][1], ph[c][2], ph[c][3], bh0, bh1);
        mma16816(o[nf2], pl[c][0], pl[c][1], pl[c][2], pl[c][3], bh0, bh1);
        u32 bl0 = *(const u32*)(smem + vb + 18432);
        u32 bl1 = *(const u32*)(smem + vb + 18432 + 16);
        mma16816(o[nf2], ph[c][0], ph[c][1], ph[c][2], ph[c][3], bl0, bl1);
      }
    }

    __syncthreads();   // buffer fully consumed
    if (tile < 126) {
      issue_tile(tile + 2, tile & 1);
      CP_COMMIT();
    }
  }

  // ---- epilogue: combine kh halves, normalize, store ----
  float* Ob = (float*)(smem + SBUF);    // 64 x 128 f32
  if (kh == 0) {
#pragma unroll
    for (int nf2 = 0; nf2 < 16; nf2++) {
      int c0 = 8 * nf2 + 2 * t;
      Ob[r0 * 128 + c0]     = o[nf2][0];
      Ob[r0 * 128 + c0 + 1] = o[nf2][1];
      Ob[r1 * 128 + c0]     = o[nf2][2];
      Ob[r1 * 128 + c0 + 1] = o[nf2][3];
    }
  }
  __syncthreads();
  if (kh == 1) {
    const float inv0 = 1.0f / l0, inv1 = 1.0f / l1;
#pragma unroll
    for (int nf2 = 0; nf2 < 16; nf2++) {
      int c0 = 8 * nf2 + 2 * t;
      float v00 = (o[nf2][0] + Ob[r0 * 128 + c0])     * inv0;
      float v01 = (o[nf2][1] + Ob[r0 * 128 + c0 + 1]) * inv0;
      float v10 = (o[nf2][2] + Ob[r1 * 128 + c0])     * inv1;
      float v11 = (o[nf2][3] + Ob[r1 * 128 + c0 + 1]) * inv1;
      *(float2*)&Out[(size_t)(qb * 64 + r0) * D_HEAD + c0] = make_float2(v00, v01);
      *(float2*)&Out[(size_t)(qb * 64 + r1) * D_HEAD + c0] = make_float2(v10, v11);
    }
  }
}

// ---------------------------------------------------------------------------
extern "C" void kernel_launch(void* const* d_in, const int* in_sizes, int n_in,
                              void* d_out, int out_size) {
  const float* x  = (const float*)d_in[0];
  const float* Wq = (const float*)d_in[1];
  const float* Wk = (const float*)d_in[2];
  const float* Wv = (const float*)d_in[3];
  float* out = (float*)d_out;

  cudaFuncSetAttribute(attn_kernel,
                       cudaFuncAttributeMaxDynamicSharedMemorySize, ATT_SMEM);

  split_x_kernel<<<(N_TOK * D_IN) / 2048, 256>>>(x);
  split_w_kernel<<<dim3((D_HEAD * D_IN) / 2048, 3), 256>>>(Wq, Wk, Wv);
  proj_mma_kernel<<<dim3(N_TOK / 128, 3), 256>>>();
  attn_kernel<<<N_TOK / 64, 256, ATT_SMEM>>>(out);
}

// round 6
// speedup vs baseline: 4.4935x; 1.0435x over previous
#include <cuda_runtime.h>
#include <cuda_bf16.h>
#include <math.h>
#include <stdint.h>

#define N_TOK 8192
#define D_IN  1024
#define D_HEAD 128

typedef uint32_t u32;

// ---------------------------------------------------------------------------
// Device-global scratch.
// ---------------------------------------------------------------------------
__device__ __align__(16) __nv_bfloat16 g_Xh[(size_t)N_TOK * D_IN];
__device__ __align__(16) __nv_bfloat16 g_Xl[(size_t)N_TOK * D_IN];
__device__ __align__(16) __nv_bfloat16 g_Wh[3 * D_HEAD * D_IN];
__device__ __align__(16) __nv_bfloat16 g_Wl[3 * D_HEAD * D_IN];
__device__ __align__(16) __nv_bfloat16 g_Qh[N_TOK * D_HEAD];
__device__ __align__(16) __nv_bfloat16 g_Ql[N_TOK * D_HEAD];
__device__ __align__(16) __nv_bfloat16 g_Kh[N_TOK * D_HEAD];
__device__ __align__(16) __nv_bfloat16 g_Kl[N_TOK * D_HEAD];
__device__ __align__(16) __nv_bfloat16 g_Vth[N_TOK * D_HEAD];
__device__ __align__(16) __nv_bfloat16 g_Vtl[N_TOK * D_HEAD];

__device__ __forceinline__ void split_bf16(float v, __nv_bfloat16& h, __nv_bfloat16& l) {
  h = __float2bfloat16(v);
  l = __float2bfloat16(v - __bfloat162float(h));
}

__device__ __forceinline__ u32 smem_u32(const void* p) {
  u32 a;
  asm("{ .reg .u64 t; cvta.to.shared.u64 t, %1; cvt.u32.u64 %0, t; }" : "=r"(a) : "l"(p));
  return a;
}
__device__ __forceinline__ void cp16(u32 dst, const void* src) {
  asm volatile("cp.async.cg.shared.global [%0], [%1], 16;" :: "r"(dst), "l"(src));
}
#define CP_COMMIT() asm volatile("cp.async.commit_group;" ::: "memory")
#define CP_WAIT0()  asm volatile("cp.async.wait_group 0;" ::: "memory")
#define CP_WAIT1()  asm volatile("cp.async.wait_group 1;" ::: "memory")
#define CP_WAIT2()  asm volatile("cp.async.wait_group 2;" ::: "memory")

// m16n8k16 row.col bf16 -> f32 (HMMA; portable PTX)
__device__ __forceinline__ void mma16816(float* d, u32 a0, u32 a1, u32 a2, u32 a3,
                                         u32 b0, u32 b1) {
  asm volatile(
      "mma.sync.aligned.m16n8k16.row.col.f32.bf16.bf16.f32 "
      "{%0,%1,%2,%3}, {%4,%5,%6,%7}, {%8,%9}, {%0,%1,%2,%3};"
      : "+f"(d[0]), "+f"(d[1]), "+f"(d[2]), "+f"(d[3])
      : "r"(a0), "r"(a1), "r"(a2), "r"(a3), "r"(b0), "r"(b1));
}
__device__ __forceinline__ u32 cvt2(float hi, float lo) {
  u32 d;
  asm("cvt.rn.bf16x2.f32 %0, %1, %2;" : "=r"(d) : "f"(hi), "f"(lo));
  return d;
}

// ---------------------------------------------------------------------------
// Split kernels: fp32 -> bf16 hi/lo.
// ---------------------------------------------------------------------------
__device__ __forceinline__ void split8_store(const float* v, __nv_bfloat16* dh,
                                             __nv_bfloat16* dl) {
  u32 hw[4], lw[4];
#pragma unroll
  for (int j = 0; j < 4; j++) {
    __nv_bfloat16 h0, l0, h1, l1;
    split_bf16(v[2 * j], h0, l0);
    split_bf16(v[2 * j + 1], h1, l1);
    hw[j] = ((u32)__bfloat16_as_ushort(h1) << 16) | __bfloat16_as_ushort(h0);
    lw[j] = ((u32)__bfloat16_as_ushort(l1) << 16) | __bfloat16_as_ushort(l0);
  }
  *(uint4*)dh = make_uint4(hw[0], hw[1], hw[2], hw[3]);
  *(uint4*)dl = make_uint4(lw[0], lw[1], lw[2], lw[3]);
}

__global__ __launch_bounds__(256) void split_x_kernel(const float* __restrict__ X) {
  size_t i = ((size_t)blockIdx.x * 256 + threadIdx.x) * 8;
  float4 f0 = *(const float4*)&X[i];
  float4 f1 = *(const float4*)&X[i + 4];
  float v[8] = {f0.x, f0.y, f0.z, f0.w, f1.x, f1.y, f1.z, f1.w};
  split8_store(v, &g_Xh[i], &g_Xl[i]);
}

__global__ __launch_bounds__(256) void split_w_kernel(
    const float* __restrict__ Wq, const float* __restrict__ Wk,
    const float* __restrict__ Wv) {
  const int y = blockIdx.y;
  const float* W = (y == 0) ? Wq : (y == 1 ? Wk : Wv);
  size_t i = ((size_t)blockIdx.x * 256 + threadIdx.x) * 8;
  float4 f0 = *(const float4*)&W[i];
  float4 f1 = *(const float4*)&W[i + 4];
  float v[8] = {f0.x, f0.y, f0.z, f0.w, f1.x, f1.y, f1.z, f1.w};
  size_t o = (size_t)y * D_HEAD * D_IN + i;
  split8_store(v, &g_Wh[o], &g_Wl[o]);
}

// ---------------------------------------------------------------------------
// HMMA projection, double-buffered k-loop. BM=128, 256 threads, 2 CTAs/SM.
// ---------------------------------------------------------------------------
#define PSTR 80
#define PXH 0
#define PXL 10240
#define PWH 20480
#define PWL 30720
#define PSTAGE 40960
#define PROJ_SMEM (2 * PSTAGE)

__global__ __launch_bounds__(256, 2) void proj_mma_kernel() {
  extern __shared__ __align__(16) char psm[];
  const u32 pb = smem_u32(psm);

  const int y = blockIdx.y;
  const int bm = blockIdx.x;
  const int tid = threadIdx.x;
  const int w = tid >> 5;
  const int lane = tid & 31;
  const int g = lane >> 2;
  const int t = lane & 3;

  const char* xh = (const char*)g_Xh;
  const char* xl = (const char*)g_Xl;
  const char* wh = (const char*)(g_Wh + (size_t)y * D_HEAD * D_IN);
  const char* wl = (const char*)(g_Wl + (size_t)y * D_HEAD * D_IN);

  auto issue_chunk = [&](int kc32, int st) {
    const u32 base = pb + st * PSTAGE;
    const int k0 = kc32 * 32;
#pragma unroll
    for (int p = 0; p < 2; p++) {
      int idx = tid + 256 * p;           // 0..511
      int row = idx >> 2, sub = idx & 3;
      int so = row * PSTR + sub * 16;
      size_t xoff = ((size_t)(bm * 128 + row) * D_IN + k0) * 2 + sub * 16;
      size_t woff = ((size_t)row * D_IN + k0) * 2 + sub * 16;
      cp16(base + PXH + so, xh + xoff);
      cp16(base + PXL + so, xl + xoff);
      cp16(base + PWH + so, wh + woff);
      cp16(base + PWL + so, wl + woff);
    }
  };

  float o[16][4];
#pragma unroll
  for (int i = 0; i < 16; i++)
#pragma unroll
    for (int j = 0; j < 4; j++) o[i][j] = 0.0f;

  issue_chunk(0, 0);
  CP_COMMIT();

#pragma unroll 1
  for (int kc32 = 0; kc32 < 32; kc32++) {
    if (kc32 < 31) {
      issue_chunk(kc32 + 1, (kc32 + 1) & 1);
      CP_COMMIT();
      CP_WAIT1();
    } else {
      CP_WAIT0();
    }
    __syncthreads();

    const char* sm = psm + (kc32 & 1) * PSTAGE;
    const int oX = (16 * w + g) * PSTR + t * 4;
#pragma unroll
    for (int kc = 0; kc < 2; kc++) {
      const int qo = oX + kc * 32;
      u32 ah0 = *(const u32*)(sm + PXH + qo);
      u32 ah1 = *(const u32*)(sm + PXH + qo + 8 * PSTR);
      u32 ah2 = *(const u32*)(sm + PXH + qo + 16);
      u32 ah3 = *(const u32*)(sm + PXH + qo + 8 * PSTR + 16);
      u32 al0 = *(const u32*)(sm + PXL + qo);
      u32 al1 = *(const u32*)(sm + PXL + qo + 8 * PSTR);
      u32 al2 = *(const u32*)(sm + PXL + qo + 16);
      u32 al3 = *(const u32*)(sm + PXL + qo + 8 * PSTR + 16);
#pragma unroll
      for (int nf = 0; nf < 16; nf++) {
        const int bo = (8 * nf + g) * PSTR + t * 4 + kc * 32;
        u32 bh0 = *(const u32*)(sm + PWH + bo);
        u32 bh1 = *(const u32*)(sm + PWH + bo + 16);
        mma16816(o[nf], ah0, ah1, ah2, ah3, bh0, bh1);
        mma16816(o[nf], al0, al1, al2, al3, bh0, bh1);
        u32 bl0 = *(const u32*)(sm + PWL + bo);
        u32 bl1 = *(const u32*)(sm + PWL + bo + 16);
        mma16816(o[nf], ah0, ah1, ah2, ah3, bl0, bl1);
      }
    }
    __syncthreads();
  }

  const float scale = 11.313708498984760f;  // sqrt(128)
#pragma unroll
  for (int nf = 0; nf < 16; nf++) {
    int c0 = 8 * nf + 2 * t;
    int R0 = bm * 128 + 16 * w + g;
#pragma unroll
    for (int q = 0; q < 4; q++) {
      int R = R0 + (q >> 1) * 8;
      int c = c0 + (q & 1);
      float v = o[nf][q];
      __nv_bfloat16 h, l;
      if (y == 0) {
        split_bf16(v * scale, h, l);
        g_Qh[(size_t)R * D_HEAD + c] = h;
        g_Ql[(size_t)R * D_HEAD + c] = l;
      } else if (y == 1) {
        split_bf16(v, h, l);
        g_Kh[(size_t)R * D_HEAD + c] = h;
        g_Kl[(size_t)R * D_HEAD + c] = l;
      } else {
        split_bf16(v, h, l);
        size_t idx = (size_t)(R >> 7) * 16384 + (size_t)c * 128 + (R & 127);
        g_Vth[idx] = h;
        g_Vtl[idx] = l;
      }
    }
  }
}

// ---------------------------------------------------------------------------
// Pipelined HMMA flash kernel, cross-tile S/softmax overlap + intra-CTA split-K.
// BM=64, BN=64/tile, 128 tiles. 8 warps: rg=w&3 rows, kh=w>>2 key-half.
// Each kh half keeps its own (m, l, O); merged in epilogue.
// ---------------------------------------------------------------------------
#define RSTR 272
#define VSTR 144
#define SQH 0
#define SQL 17408
#define SBUF 34816
#define BKH 0
#define BKL 17408
#define BVH 34816
#define BVL 53248
#define BUFSZ 71680
#define SRED (SBUF + 2 * BUFSZ)        // 178176
#define ATT_SMEM (SRED + 1024)

__global__ __launch_bounds__(256, 1) void attn_kernel(float* __restrict__ Out) {
  extern __shared__ __align__(16) char smem[];
  const u32 sb = smem_u32(smem);

  const int tid = threadIdx.x;
  const int w = tid >> 5;
  const int lane = tid & 31;
  const int g = lane >> 2;
  const int t = lane & 3;
  const int rg = w & 3;
  const int kh = w >> 2;
  const int qb = blockIdx.x;
  const int r0 = 16 * rg + g;
  const int r1 = r0 + 8;

  auto issue_K = [&](int tile, int b) {
    const u32 base = sb + SBUF + b * BUFSZ;
    const char* gkh = (const char*)g_Kh + (size_t)tile * 16384;
    const char* gkl = (const char*)g_Kl + (size_t)tile * 16384;
#pragma unroll
    for (int p = 0; p < 4; p++) {
      int idx = tid + 256 * p;           // 0..1023
      int kr = idx >> 4, ks = idx & 15;
      int so = kr * RSTR + ks * 16;
      cp16(base + BKH + so, gkh + idx * 16);
      cp16(base + BKL + so, gkl + idx * 16);
    }
  };
  auto issue_V = [&](int tile, int b) {
    const u32 base = sb + SBUF + b * BUFSZ;
    const size_t vbase = (size_t)(tile >> 1) * 32768 + (size_t)(tile & 1) * 128;
    const char* gvh = (const char*)g_Vth + vbase;
    const char* gvl = (const char*)g_Vtl + vbase;
#pragma unroll
    for (int p = 0; p < 4; p++) {
      int idx = tid + 256 * p;           // 0..1023
      int vd = idx >> 3, vs = idx & 7;
      int so = vd * VSTR + vs * 16;
      size_t voff = (size_t)vd * 256 + vs * 16;
      cp16(base + BVH + so, gvh + voff);
      cp16(base + BVL + so, gvl + voff);
    }
  };

  const int oQ = SQH + r0 * RSTR + t * 4;

  // S-phase MMA block: s += Q(rows) * K(buf b)^T for this warp's 32 keys
  auto mma_S = [&](float s[4][4], int b) {
    const int oK = SBUF + b * BUFSZ + BKH + (32 * kh + g) * RSTR + t * 4;
#pragma unroll
    for (int kc = 0; kc < 8; kc++) {
      const int qo = oQ + kc * 32;
      u32 ah0 = *(const u32*)(smem + qo);
      u32 ah1 = *(const u32*)(smem + qo + 8 * RSTR);
      u32 ah2 = *(const u32*)(smem + qo + 16);
      u32 ah3 = *(const u32*)(smem + qo + 8 * RSTR + 16);
      u32 al0 = *(const u32*)(smem + qo + 17408);
      u32 al1 = *(const u32*)(smem + qo + 17408 + 8 * RSTR);
      u32 al2 = *(const u32*)(smem + qo + 17408 + 16);
      u32 al3 = *(const u32*)(smem + qo + 17408 + 8 * RSTR + 16);
#pragma unroll
      for (int nf = 0; nf < 4; nf++) {
        const int bo = oK + nf * 8 * RSTR + kc * 32;
        u32 bh0 = *(const u32*)(smem + bo);
        u32 bh1 = *(const u32*)(smem + bo + 16);
        mma16816(s[nf], ah0, ah1, ah2, ah3, bh0, bh1);
        mma16816(s[nf], al0, al1, al2, al3, bh0, bh1);
        u32 bl0 = *(const u32*)(smem + bo + 17408);
        u32 bl1 = *(const u32*)(smem + bo + 17408 + 16);
        mma16816(s[nf], ah0, ah1, ah2, ah3, bl0, bl1);
      }
    }
  };

  // ---- prologue: Q + K0 + V0 (g0); K1 (g1); V1 (g2) ----
  {
    const char* gqh = (const char*)g_Qh + (size_t)qb * 16384;
    const char* gql = (const char*)g_Ql + (size_t)qb * 16384;
#pragma unroll
    for (int p = 0; p < 4; p++) {
      int idx = tid + 256 * p;
      int row = idx >> 4, sub = idx & 15;
      int so = row * RSTR + sub * 16;
      cp16(sb + SQH + so, gqh + idx * 16);
      cp16(sb + SQL + so, gql + idx * 16);
    }
    issue_K(0, 0);
    issue_V(0, 0);
    CP_COMMIT();
    issue_K(1, 1);
    CP_COMMIT();
    issue_V(1, 1);
    CP_COMMIT();
  }

  float o[16][4];
#pragma unroll
  for (int i = 0; i < 16; i++)
#pragma unroll
    for (int j = 0; j < 4; j++) o[i][j] = 0.0f;
  float m0 = -1e30f, m1 = -1e30f, l0 = 0.0f, l1 = 0.0f;

  float s_cur[4][4], s_next[4][4];

  // S(0)
  CP_WAIT2();
  __syncthreads();
#pragma unroll
  for (int i = 0; i < 4; i++)
#pragma unroll
    for (int j = 0; j < 4; j++) s_cur[i][j] = 0.0f;
  mma_S(s_cur, 0);

#pragma unroll 1
  for (int tile = 0; tile < 128; ++tile) {
    if (tile < 127) CP_WAIT1(); else CP_WAIT0();
    __syncthreads();

    // prefetch K(t+2) into Kbuf t&1 (its old K consumed last iteration)
    if (tile < 126) {
      issue_K(tile + 2, tile & 1);
      CP_COMMIT();
    }

    // ---- phase A: S(t+1) (independent of softmax/PV below) ----
    if (tile < 127) {
#pragma unroll
      for (int i = 0; i < 4; i++)
#pragma unroll
        for (int j = 0; j < 4; j++) s_next[i][j] = 0.0f;
      mma_S(s_next, (tile + 1) & 1);
    }

    // ---- phase B: warp-local softmax on s_cur (per-kh split-K state) ----
    float mt0 = -1e30f, mt1 = -1e30f;
#pragma unroll
    for (int nf = 0; nf < 4; nf++) {
      mt0 = fmaxf(mt0, fmaxf(s_cur[nf][0], s_cur[nf][1]));
      mt1 = fmaxf(mt1, fmaxf(s_cur[nf][2], s_cur[nf][3]));
    }
#pragma unroll
    for (int off = 1; off <= 2; off <<= 1) {
      mt0 = fmaxf(mt0, __shfl_xor_sync(0xffffffffu, mt0, off));
      mt1 = fmaxf(mt1, __shfl_xor_sync(0xffffffffu, mt1, off));
    }
    const float mn0 = fmaxf(m0, mt0), mn1 = fmaxf(m1, mt1);
    const float a0f = __expf(m0 - mn0), a1f = __expf(m1 - mn1);
    m0 = mn0; m1 = mn1;

    float sum0 = 0.0f, sum1 = 0.0f;
#pragma unroll
    for (int nf = 0; nf < 4; nf++) {
      s_cur[nf][0] = __expf(s_cur[nf][0] - mn0); sum0 += s_cur[nf][0];
      s_cur[nf][1] = __expf(s_cur[nf][1] - mn0); sum0 += s_cur[nf][1];
      s_cur[nf][2] = __expf(s_cur[nf][2] - mn1); sum1 += s_cur[nf][2];
      s_cur[nf][3] = __expf(s_cur[nf][3] - mn1); sum1 += s_cur[nf][3];
    }
#pragma unroll
    for (int off = 1; off <= 2; off <<= 1) {
      sum0 += __shfl_xor_sync(0xffffffffu, sum0, off);
      sum1 += __shfl_xor_sync(0xffffffffu, sum1, off);
    }
    l0 = l0 * a0f + sum0;
    l1 = l1 * a1f + sum1;

#pragma unroll
    for (int i = 0; i < 16; i++) {
      o[i][0] *= a0f; o[i][1] *= a0f;
      o[i][2] *= a1f; o[i][3] *= a1f;
    }

    // ---- pack P hi/lo into PV A-frags (registers only) ----
    u32 ph[2][4], pl[2][4];
#pragma unroll
    for (int c = 0; c < 2; c++) {
      float e[8] = { s_cur[2*c][0],   s_cur[2*c][1],   s_cur[2*c][2],   s_cur[2*c][3],
                     s_cur[2*c+1][0], s_cur[2*c+1][1], s_cur[2*c+1][2], s_cur[2*c+1][3] };
      const int map[4][2] = {{0,1},{2,3},{4,5},{6,7}};
#pragma unroll
      for (int q = 0; q < 4; q++) {
        float x0 = e[map[q][0]], x1 = e[map[q][1]];
        u32 hp = cvt2(x1, x0);
        float h0 = __uint_as_float(hp << 16);
        float h1 = __uint_as_float(hp & 0xffff0000u);
        ph[c][q] = hp;
        pl[c][q] = cvt2(x1 - h1, x0 - h0);
      }
    }

    // ---- O += P V over this warp's 32 keys ----
    const int oV = SBUF + (tile & 1) * BUFSZ + BVH + g * VSTR + t * 4 + kh * 64;
#pragma unroll
    for (int c = 0; c < 2; c++) {
#pragma unroll
      for (int nf2 = 0; nf2 < 16; nf2++) {
        const int vb = oV + nf2 * 8 * VSTR + c * 32;
        u32 bh0 = *(const u32*)(smem + vb);
        u32 bh1 = *(const u32*)(smem + vb + 16);
        mma16816(o[nf2], ph[c][0], ph[c][1], ph[c][2], ph[c][3], bh0, bh1);
        mma16816(o[nf2], pl[c][0], pl[c][1], pl[c][2], pl[c][3], bh0, bh1);
        u32 bl0 = *(const u32*)(smem + vb + 18432);
        u32 bl1 = *(const u32*)(smem + vb + 18432 + 16);
        mma16816(o[nf2], ph[c][0], ph[c][1], ph[c][2], ph[c][3], bl0, bl1);
      }
    }

    __syncthreads();   // V buffer fully consumed
    if (tile < 126) {
      issue_V(tile + 2, tile & 1);
      CP_COMMIT();
    }

    // rotate S double buffer
#pragma unroll
    for (int i = 0; i < 4; i++)
#pragma unroll
      for (int j = 0; j < 4; j++) s_cur[i][j] = s_next[i][j];
  }

  // ---- epilogue: merge kh=0 / kh=1 split-K states, normalize, store ----
  float* Ob = (float*)(smem + SBUF);    // 64 x 128 f32
  float* redm = (float*)(smem + SRED);
  float* redl = redm + 64;
  if (kh == 0) {
#pragma unroll
    for (int nf2 = 0; nf2 < 16; nf2++) {
      int c0 = 8 * nf2 + 2 * t;
      Ob[r0 * 128 + c0]     = o[nf2][0];
      Ob[r0 * 128 + c0 + 1] = o[nf2][1];
      Ob[r1 * 128 + c0]     = o[nf2][2];
      Ob[r1 * 128 + c0 + 1] = o[nf2][3];
    }
    if (t == 0) {
      redm[r0] = m0; redl[r0] = l0;
      redm[r1] = m1; redl[r1] = l1;
    }
  }
  __syncthreads();
  if (kh == 1) {
    float pm0 = redm[r0], pl0 = redl[r0];
    float pm1 = redm[r1], pl1 = redl[r1];
    float M0 = fmaxf(m0, pm0), M1 = fmaxf(m1, pm1);
    float w1_0 = __expf(m0 - M0), w0_0 = __expf(pm0 - M0);
    float w1_1 = __expf(m1 - M1), w0_1 = __expf(pm1 - M1);
    float inv0 = 1.0f / (w0_0 * pl0 + w1_0 * l0);
    float inv1 = 1.0f / (w0_1 * pl1 + w1_1 * l1);
#pragma unroll
    for (int nf2 = 0; nf2 < 16; nf2++) {
      int c0 = 8 * nf2 + 2 * t;
      float v00 = (w1_0 * o[nf2][0] + w0_0 * Ob[r0 * 128 + c0])     * inv0;
      float v01 = (w1_0 * o[nf2][1] + w0_0 * Ob[r0 * 128 + c0 + 1]) * inv0;
      float v10 = (w1_1 * o[nf2][2] + w0_1 * Ob[r1 * 128 + c0])     * inv1;
      float v11 = (w1_1 * o[nf2][3] + w0_1 * Ob[r1 * 128 + c0 + 1]) * inv1;
      *(float2*)&Out[(size_t)(qb * 64 + r0) * D_HEAD + c0] = make_float2(v00, v01);
      *(float2*)&Out[(size_t)(qb * 64 + r1) * D_HEAD + c0] = make_float2(v10, v11);
    }
  }
}

// ---------------------------------------------------------------------------
extern "C" void kernel_launch(void* const* d_in, const int* in_sizes, int n_in,
                              void* d_out, int out_size) {
  const float* x  = (const float*)d_in[0];
  const float* Wq = (const float*)d_in[1];
  const float* Wk = (const float*)d_in[2];
  const float* Wv = (const float*)d_in[3];
  float* out = (float*)d_out;

  cudaFuncSetAttribute(attn_kernel,
                       cudaFuncAttributeMaxDynamicSharedMemorySize, ATT_SMEM);
  cudaFuncSetAttribute(proj_mma_kernel,
                       cudaFuncAttributeMaxDynamicSharedMemorySize, PROJ_SMEM);

  split_x_kernel<<<(N_TOK * D_IN) / 2048, 256>>>(x);
  split_w_kernel<<<dim3((D_HEAD * D_IN) / 2048, 3), 256>>>(Wq, Wk, Wv);
  proj_mma_kernel<<<dim3(N_TOK / 128, 3), 256, PROJ_SMEM>>>();
  attn_kernel<<<N_TOK / 64, 256, ATT_SMEM>>>(out);
}